// round 15
// baseline (speedup 1.0000x reference)
#include <cuda_runtime.h>
#include <cuda_fp16.h>
#include <mma.h>
using namespace nvcuda;

#define NN 100000
#define NE 1600000
#define NG 256
#define HID 64
#define NEP (NE + 3 * NN + 16)   // padded edge capacity + pipeline slack

// ---- static scratch (no allocations allowed) ----
__device__ __align__(16) __half g_xwA[NN * HID];
__device__ __align__(16) __half g_xwB[NN * HID];
__device__ unsigned long long g_packed[NN];        // [40:64)=count, [0:40)=sum(w) Q24
__device__ float g_deg[NN];                        // dinv = rsqrt(deg)
__device__ int   g_row[NN + 1];                    // padded CSR row offsets (by dst)
__device__ __align__(8) int2 g_nodeinfo[NN];       // (padded row offset, dinv-as-bits)
__device__ int   g_rank[NE];                       // per-edge rank within dst bucket
__device__ unsigned long long g_lbpack[128];       // lookback state
__device__ __align__(16) int2 g_edge[NEP];         // record: (src<<7 byte-off, norm as half2)
__device__ float g_sums[NG];
__device__ float g_cnt[NG];

#define Q24 16777216.0f

#define SA 72   // half matrix smem stride
#define SC 68   // float C smem stride
#define SB2 40  // readout B stride
#define SC2 36  // readout C stride

// -------------------- deg + hist + rank (one packed 64b atomic) --------------------
__global__ void k_deg_hist(const int* __restrict__ dst, const float* __restrict__ w, int E) {
    int e = blockIdx.x * blockDim.x + threadIdx.x;
    if (e < E) {
        int d = dst[e];
        unsigned long long add =
            (1ull << 40) | (unsigned long long)__float2uint_rn(w[e] * Q24);
        unsigned long long old = atomicAdd(&g_packed[d], add);
        g_rank[e] = (int)(old >> 40);
    }
}

// -------------------- single-pass decoupled-lookback scan (over PADDED counts) ------
__global__ __launch_bounds__(1024) void k_scan(int n) {
    __shared__ int ws[32];
    __shared__ int prefix_s;
    int b = blockIdx.x, t = threadIdx.x;
    int i = b * 1024 + t;
    unsigned long long pk = (i < n) ? g_packed[i] : 0ull;
    int c = (int)(pk >> 40);
    int cpad = (c + 3) & ~3;                // pad bucket to multiple of 4 edges
    if (i < n) g_packed[i] = 0ull;          // reset for next launch

    const unsigned full = 0xffffffffu;
    int lane = t & 31, warp = t >> 5;
    int x = cpad;
    #pragma unroll
    for (int off = 1; off < 32; off <<= 1) {
        int y = __shfl_up_sync(full, x, off);
        if (lane >= off) x += y;
    }
    if (lane == 31) ws[warp] = x;
    __syncthreads();
    if (warp == 0) {
        int y = ws[lane];
        #pragma unroll
        for (int off = 1; off < 32; off <<= 1) {
            int z = __shfl_up_sync(full, y, off);
            if (lane >= off) y += z;
        }
        ws[lane] = y;
    }
    __syncthreads();
    int blockpref = (warp > 0) ? ws[warp - 1] : 0;
    int incl = x + blockpref;

    if (t == 1023) {
        unsigned long long p = (1ull << 32) | (unsigned)incl;
        *((volatile unsigned long long*)&g_lbpack[b]) = p;
    }
    if (t == 0) prefix_s = 0;
    __syncthreads();
    if (t < b) {
        unsigned long long p;
        do { p = *((volatile unsigned long long*)&g_lbpack[t]); } while (!(p >> 32));
        atomicAdd(&prefix_s, (int)(unsigned)p);
    }
    __syncthreads();

    int excl = incl - cpad + prefix_s;
    if (i < n) {
        g_row[i] = excl;
        float deg = 1.0f + (float)(pk & 0xFFFFFFFFFFull) * (1.0f / Q24);
        float dinv = rsqrtf(deg);
        g_deg[i] = dinv;
        int2 ni; ni.x = excl; ni.y = __float_as_int(dinv);
        g_nodeinfo[i] = ni;
        int2 z; z.x = 0; z.y = 0;          // half2(0,0) pad: contributes exactly 0
        for (int k = c; k < cpad; k++) g_edge[excl + k] = z;
    }
    if (i == n) g_row[n] = excl;
}

// -------------------- merged: CSR fill + layer-0 GEMM (wmma) --------------------
__global__ __launch_bounds__(256) void k_fill_gemm0(
    const int* __restrict__ src, const int* __restrict__ dst,
    const float* __restrict__ w, int E,
    const float* __restrict__ X, const float* __restrict__ W, int n,
    int gemm_blocks)
{
    __shared__ __half WsH[64 * SA];
    __shared__ __half XsH[64 * SA];
    __shared__ float Cs[64 * SC];

    int tid = threadIdx.x;

    if (blockIdx.x >= gemm_blocks) {
        // ---- fill part (norm stored as duplicated half2) ----
        int e = (blockIdx.x - gemm_blocks) * 256 + tid;
        if (e < E) {
            int s = src[e], d = dst[e];
            int2 di = __ldg(g_nodeinfo + d);
            float nv = __ldg(g_deg + s) * w[e] * __int_as_float(di.y);
            int pos = di.x + g_rank[e];
            __half2 nh2 = __half2half2(__float2half_rn(nv));
            int2 rec; rec.x = s << 7; rec.y = *(int*)&nh2;
            g_edge[pos] = rec;
        }
        return;
    }

    // ---- gemm0: xwA = X @ W0 via wmma ----
    int row0 = blockIdx.x * 64;

    const float4* W4 = (const float4*)W;
    #pragma unroll
    for (int i = 0; i < 4; i++) {
        int idx = tid + 256 * i;
        float4 f = W4[idx];
        int k = idx >> 4, c4 = idx & 15;
        __half2 h0 = __floats2half2_rn(f.x, f.y);
        __half2 h1 = __floats2half2_rn(f.z, f.w);
        uint2 u; u.x = *(unsigned*)&h0; u.y = *(unsigned*)&h1;
        *(uint2*)&WsH[k * SA + c4 * 4] = u;
    }
    const float4* X4 = (const float4*)(X + (size_t)row0 * 64);
    #pragma unroll
    for (int i = 0; i < 4; i++) {
        int idx = tid + 256 * i;
        int r = idx >> 4, c4 = idx & 15;
        if (row0 + r < n) {
            float4 f = X4[idx];
            __half2 h0 = __floats2half2_rn(f.x, f.y);
            __half2 h1 = __floats2half2_rn(f.z, f.w);
            uint2 u; u.x = *(unsigned*)&h0; u.y = *(unsigned*)&h1;
            *(uint2*)&XsH[r * SA + c4 * 4] = u;
        }
    }
    __syncthreads();

    int wp = tid >> 5;
    int tile_r = wp & 3;
    #pragma unroll
    for (int t2 = 0; t2 < 2; t2++) {
        int tile_c = (wp >> 2) * 2 + t2;
        wmma::fragment<wmma::accumulator, 16, 16, 16, float> cf;
        wmma::fill_fragment(cf, 0.f);
        #pragma unroll
        for (int kk = 0; kk < 4; kk++) {
            wmma::fragment<wmma::matrix_a, 16, 16, 16, __half, wmma::row_major> af;
            wmma::fragment<wmma::matrix_b, 16, 16, 16, __half, wmma::row_major> bf;
            wmma::load_matrix_sync(af, XsH + tile_r * 16 * SA + kk * 16, SA);
            wmma::load_matrix_sync(bf, WsH + kk * 16 * SA + tile_c * 16, SA);
            wmma::mma_sync(cf, af, bf, cf);
        }
        wmma::store_matrix_sync(Cs + tile_r * 16 * SC + tile_c * 16, cf, SC, wmma::mem_row_major);
    }
    __syncthreads();

    int r = tid >> 2, c0 = (tid & 3) * 16;
    int row = row0 + r;
    if (row >= n) return;
    const float* crow = &Cs[r * SC + c0];
    __half2 hh[8];
    #pragma unroll
    for (int i = 0; i < 8; i++) hh[i] = __floats2half2_rn(crow[2 * i], crow[2 * i + 1]);
    uint4* dstp = (uint4*)(g_xwA + (size_t)row * 64 + c0);
    dstp[0] = ((uint4*)hh)[0];
    dstp[1] = ((uint4*)hh)[1];
}

// ---- gather core: 8 threads/node, DOUBLE-BUFFERED feature pipeline ----
// Records of group i+1 are prefetched in iteration i-1, so feature loads of
// group i+1 issue during iteration i -> 8 feature loads in flight per thread.
__device__ __forceinline__ void gather_core8(const __half* __restrict__ xwh,
                                             int node, int j,
                                             const float* __restrict__ bias,
                                             float* a /*[8]*/)
{
    int2 ni = __ldg(g_nodeinfo + node);      // (padded start, dinv)
    int start = ni.x;
    int end   = __ldg(g_row + node + 1);
    float dv = __int_as_float(ni.y);
    float inv = dv * dv;

    const char* base = (const char*)xwh + (j << 4);

    // bias + self-loop in fp32 (exact path)
    {
        uint4 v = __ldg((const uint4*)(base + ((unsigned)node << 7)));
        const __half2* h = (const __half2*)&v;
        const float4* b4 = (const float4*)(bias + j * 8);
        float4 b0 = __ldg(b4), b1 = __ldg(b4 + 1);
        float2 f0 = __half22float2(h[0]), f1 = __half22float2(h[1]);
        float2 f2 = __half22float2(h[2]), f3 = __half22float2(h[3]);
        a[0] = f0.x * inv + b0.x; a[1] = f0.y * inv + b0.y;
        a[2] = f1.x * inv + b0.z; a[3] = f1.y * inv + b0.w;
        a[4] = f2.x * inv + b1.x; a[5] = f2.y * inv + b1.y;
        a[6] = f3.x * inv + b1.z; a[7] = f3.y * inv + b1.w;
    }

    const int4* ep = (const int4*)(g_edge + start);   // 2 records per int4
    int groups = (end - start) >> 2;                  // exact (padded)

    // prologue: records + features of group 0 (slack makes OOB reads safe/valid)
    int4 r01 = __ldg(ep);
    int4 r23 = __ldg(ep + 1);
    uint4 u0 = __ldg((const uint4*)(base + (unsigned)r01.x));
    uint4 u1 = __ldg((const uint4*)(base + (unsigned)r01.z));
    uint4 u2 = __ldg((const uint4*)(base + (unsigned)r23.x));
    uint4 u3 = __ldg((const uint4*)(base + (unsigned)r23.z));
    __half2 n0 = *(__half2*)&r01.y, n1 = *(__half2*)&r01.w;
    __half2 n2 = *(__half2*)&r23.y, n3 = *(__half2*)&r23.w;

    for (int gq = 0; gq < groups; gq++) {
        // issue next group's record + feature loads (addresses known: records first)
        int4 s01 = __ldg(ep + 2);
        int4 s23 = __ldg(ep + 3);
        ep += 2;
        uint4 v0 = __ldg((const uint4*)(base + (unsigned)s01.x));
        uint4 v1 = __ldg((const uint4*)(base + (unsigned)s01.z));
        uint4 v2 = __ldg((const uint4*)(base + (unsigned)s23.x));
        uint4 v3 = __ldg((const uint4*)(base + (unsigned)s23.z));

        // accumulate current group in fp16, flush to fp32
        const __half2* h0 = (const __half2*)&u0;
        const __half2* h1 = (const __half2*)&u1;
        const __half2* h2 = (const __half2*)&u2;
        const __half2* h3 = (const __half2*)&u3;
        __half2 s0 = __hmul2(h0[0], n0), s1 = __hmul2(h0[1], n0);
        __half2 s2 = __hmul2(h0[2], n0), s3 = __hmul2(h0[3], n0);
        s0 = __hfma2(h1[0], n1, s0); s1 = __hfma2(h1[1], n1, s1);
        s2 = __hfma2(h1[2], n1, s2); s3 = __hfma2(h1[3], n1, s3);
        s0 = __hfma2(h2[0], n2, s0); s1 = __hfma2(h2[1], n2, s1);
        s2 = __hfma2(h2[2], n2, s2); s3 = __hfma2(h2[3], n2, s3);
        s0 = __hfma2(h3[0], n3, s0); s1 = __hfma2(h3[1], n3, s1);
        s2 = __hfma2(h3[2], n3, s2); s3 = __hfma2(h3[3], n3, s3);
        float2 f;
        f = __half22float2(s0); a[0] += f.x; a[1] += f.y;
        f = __half22float2(s1); a[2] += f.x; a[3] += f.y;
        f = __half22float2(s2); a[4] += f.x; a[5] += f.y;
        f = __half22float2(s3); a[6] += f.x; a[7] += f.y;

        u0 = v0; u1 = v1; u2 = v2; u3 = v3;
        n0 = *(__half2*)&s01.y; n1 = *(__half2*)&s01.w;
        n2 = *(__half2*)&s23.y; n3 = *(__half2*)&s23.w;
    }
}

// -------------------- fused: gather -> relu(fp16 smem) -> wmma @W -> xw out ----------
__global__ __launch_bounds__(512) void k_fused(
    const float* __restrict__ bias, const float* __restrict__ W,
    int in_is_A, int n)
{
    __shared__ __half WsH[64 * SA];
    __shared__ __half XsH[64 * SA];
    __shared__ float Cs[64 * SC];

    const __half* xin = in_is_A ? g_xwA : g_xwB;
    __half* xout      = in_is_A ? g_xwB : g_xwA;

    int tid = threadIdx.x;
    int row0 = blockIdx.x * 64;

    const float4* W4 = (const float4*)W;
    #pragma unroll
    for (int i = 0; i < 2; i++) {
        int idx = tid + 512 * i;
        float4 f = W4[idx];
        int k = idx >> 4, c4 = idx & 15;
        __half2 h0 = __floats2half2_rn(f.x, f.y);
        __half2 h1 = __floats2half2_rn(f.z, f.w);
        uint2 u; u.x = *(unsigned*)&h0; u.y = *(unsigned*)&h1;
        *(uint2*)&WsH[k * SA + c4 * 4] = u;
    }

    int node_l = tid >> 3;
    int j = tid & 7;
    int node = row0 + node_l;

    if (node < n) {
        float a[8];
        gather_core8(xin, node, j, bias, a);
        __half2 hh[4];
        #pragma unroll
        for (int q = 0; q < 4; q++)
            hh[q] = __floats2half2_rn(fmaxf(a[2 * q], 0.f), fmaxf(a[2 * q + 1], 0.f));
        *(uint4*)&XsH[node_l * SA + j * 8] = *(uint4*)hh;
    } else {
        uint4 z = {0, 0, 0, 0};
        *(uint4*)&XsH[node_l * SA + j * 8] = z;
    }
    __syncthreads();

    {
        int wp = tid >> 5;
        int tile_r = wp & 3, tile_c = wp >> 2;
        wmma::fragment<wmma::accumulator, 16, 16, 16, float> cf;
        wmma::fill_fragment(cf, 0.f);
        #pragma unroll
        for (int kk = 0; kk < 4; kk++) {
            wmma::fragment<wmma::matrix_a, 16, 16, 16, __half, wmma::row_major> af;
            wmma::fragment<wmma::matrix_b, 16, 16, 16, __half, wmma::row_major> bf;
            wmma::load_matrix_sync(af, XsH + tile_r * 16 * SA + kk * 16, SA);
            wmma::load_matrix_sync(bf, WsH + kk * 16 * SA + tile_c * 16, SA);
            wmma::mma_sync(cf, af, bf, cf);
        }
        wmma::store_matrix_sync(Cs + tile_r * 16 * SC + tile_c * 16, cf, SC, wmma::mem_row_major);
    }
    __syncthreads();

    if (node >= n) return;
    const float* crow = &Cs[node_l * SC + j * 8];
    __half2 hh[4];
    #pragma unroll
    for (int q = 0; q < 4; q++) hh[q] = __floats2half2_rn(crow[2 * q], crow[2 * q + 1]);
    *(uint4*)(xout + (size_t)node * 64 + j * 8) = *(uint4*)hh;
}

// -------------------- final: gather -> wmma MLP readout -> pooled mean --------------
__global__ __launch_bounds__(512) void k_gather_readout(
    const float* __restrict__ bias,
    const float* __restrict__ Wr0, const float* __restrict__ br0,
    const float* __restrict__ Wr1, const float* __restrict__ br1,
    const int* __restrict__ batch, int n)
{
    __shared__ __half aggH[64 * SA];
    __shared__ __half W0H[64 * SB2];
    __shared__ float Cs[64 * SC2];
    __shared__ float W1s[32];
    __shared__ float b0s[32];

    int tid = threadIdx.x;
    {
        const float4* W4 = (const float4*)Wr0;
        float4 f = W4[tid];
        int k = tid >> 3, c4 = tid & 7;
        __half2 h0 = __floats2half2_rn(f.x, f.y);
        __half2 h1 = __floats2half2_rn(f.z, f.w);
        uint2 u; u.x = *(unsigned*)&h0; u.y = *(unsigned*)&h1;
        *(uint2*)&W0H[k * SB2 + c4 * 4] = u;
    }
    if (tid < 32) { W1s[tid] = Wr1[tid]; b0s[tid] = br0[tid]; }

    int node_l = tid >> 3;
    int j = tid & 7;
    int node = blockIdx.x * 64 + node_l;
    bool valid = (node < n);

    if (valid) {
        float a[8];
        gather_core8(g_xwA, node, j, bias, a);   // no relu on last GNN layer
        __half2 hh[4];
        #pragma unroll
        for (int q = 0; q < 4; q++) hh[q] = __floats2half2_rn(a[2 * q], a[2 * q + 1]);
        *(uint4*)&aggH[node_l * SA + j * 8] = *(uint4*)hh;
    } else {
        uint4 z = {0, 0, 0, 0};
        *(uint4*)&aggH[node_l * SA + j * 8] = z;
    }
    __syncthreads();

    {
        int wp = tid >> 5;
        if (wp < 8) {
            int tile_r = wp & 3, tile_c = wp >> 2;
            wmma::fragment<wmma::accumulator, 16, 16, 16, float> cf;
            wmma::fill_fragment(cf, 0.f);
            #pragma unroll
            for (int kk = 0; kk < 4; kk++) {
                wmma::fragment<wmma::matrix_a, 16, 16, 16, __half, wmma::row_major> af;
                wmma::fragment<wmma::matrix_b, 16, 16, 16, __half, wmma::row_major> bf;
                wmma::load_matrix_sync(af, aggH + tile_r * 16 * SA + kk * 16, SA);
                wmma::load_matrix_sync(bf, W0H + kk * 16 * SB2 + tile_c * 16, SB2);
                wmma::mma_sync(cf, af, bf, cf);
            }
            wmma::store_matrix_sync(Cs + tile_r * 16 * SC2 + tile_c * 16, cf, SC2, wmma::mem_row_major);
        }
    }
    __syncthreads();

    float s = 0.f, cv = 0.f;
    int g = -1;
    if (valid) {
        int c0 = j * 4;
        const float* crow = &Cs[node_l * SC2 + c0];
        const float4 w1 = *(const float4*)&W1s[c0];
        float a0 = crow[0] + b0s[c0 + 0];
        float a1 = crow[1] + b0s[c0 + 1];
        float a2 = crow[2] + b0s[c0 + 2];
        float a3 = crow[3] + b0s[c0 + 3];
        s = fmaxf(a0, 0.f) * w1.x + fmaxf(a1, 0.f) * w1.y
          + fmaxf(a2, 0.f) * w1.z + fmaxf(a3, 0.f) * w1.w;
        g = __ldg(batch + node);
    }

    const unsigned full = 0xffffffffu;
    s += __shfl_xor_sync(full, s, 4);
    s += __shfl_xor_sync(full, s, 2);
    s += __shfl_xor_sync(full, s, 1);

    if (valid && j == 0) { s += __ldg(br1); cv = 1.f; }
    else { s = 0.f; cv = 0.f; }

    int lane = tid & 31;
    #pragma unroll
    for (int off = 1; off < 32; off <<= 1) {
        float so = __shfl_up_sync(full, s, off);
        float co = __shfl_up_sync(full, cv, off);
        int go = __shfl_up_sync(full, g, off);
        if (lane >= off && go == g) { s += so; cv += co; }
    }
    int gn = __shfl_down_sync(full, g, 1);
    if ((lane == 31 || gn != g) && g >= 0) {
        atomicAdd(&g_sums[g], s);
        atomicAdd(&g_cnt[g], cv);
    }
}

// finalize output + reset accumulators/lookback for next launch
__global__ void k_finalize(float* __restrict__ out) {
    int g = threadIdx.x;
    out[g] = g_sums[g] / fmaxf(g_cnt[g], 1.0f);
    g_sums[g] = 0.f;
    g_cnt[g] = 0.f;
    if (g < 128) g_lbpack[g] = 0ull;
}

// -------------------- launch --------------------
extern "C" void kernel_launch(void* const* d_in, const int* in_sizes, int n_in,
                              void* d_out, int out_size)
{
    const float* x   = (const float*)d_in[0];
    const int*   ei  = (const int*)d_in[1];
    const float* ew  = (const float*)d_in[2];
    const int* batch = (const int*)d_in[3];
    const float* W0  = (const float*)d_in[4];
    const float* b0  = (const float*)d_in[5];
    const float* W1  = (const float*)d_in[6];
    const float* b1  = (const float*)d_in[7];
    const float* W2  = (const float*)d_in[8];
    const float* b2  = (const float*)d_in[9];
    const float* Wr0 = (const float*)d_in[10];
    const float* br0 = (const float*)d_in[11];
    const float* Wr1 = (const float*)d_in[12];
    const float* br1 = (const float*)d_in[13];
    float* out = (float*)d_out;

    int n = in_sizes[0] / HID;       // 100000
    int E = in_sizes[2];             // 1600000
    const int* src = ei;
    const int* dst = ei + E;

    int nb = (n + 1023) / 1024;      // 98 blocks: all resident -> lookback safe
    int gb = (n + 63) / 64;          // 1563 gemm/gather blocks
    int fb = (E + 255) / 256;        // 6250 fill blocks

    // launch #3 (0-indexed) is k_fused -> that's what ncu captures
    k_deg_hist<<<fb, 256>>>(dst, ew, E);                                // 0
    k_scan<<<nb, 1024>>>(n);                                            // 1
    k_fill_gemm0<<<gb + fb, 256>>>(src, dst, ew, E, x, W0, n, gb);      // 2
    k_fused<<<gb, 512>>>(b0, W1, 1, n);                                 // 3  <- profiled
    k_fused<<<gb, 512>>>(b1, W2, 0, n);                                 // 4
    k_gather_readout<<<gb, 512>>>(b2, Wr0, br0, Wr1, br1, batch, n);    // 5
    k_finalize<<<1, 256>>>(out);                                        // 6
}

// round 16
// speedup vs baseline: 1.0894x; 1.0894x over previous
#include <cuda_runtime.h>
#include <cuda_fp16.h>
#include <mma.h>
using namespace nvcuda;

#define NN 100000
#define NE 1600000
#define NG 256
#define HID 64
#define NEP (NE + 3 * NN + 16)   // padded edge capacity + slack

// ---- static scratch (no allocations allowed) ----
__device__ __align__(16) __half g_xwA[NN * HID];
__device__ __align__(16) __half g_xwB[NN * HID];
__device__ unsigned long long g_packed[NN];        // [40:64)=count, [0:40)=sum(w) Q24
__device__ float g_deg[NN];                        // dinv = rsqrt(deg)
__device__ int   g_row[NN + 1];                    // padded CSR row offsets (by dst)
__device__ __align__(8) int2 g_nodeinfo[NN];       // (padded row offset, dinv-as-bits)
__device__ int   g_rank[NE];                       // per-edge rank within dst bucket
__device__ unsigned long long g_lbpack[128];       // lookback state
__device__ __align__(16) int2 g_edge[NEP];         // record: (src<<7 byte-off, norm as half2)
__device__ float g_sums[NG];
__device__ float g_cnt[NG];

#define Q24 16777216.0f

#define SA 72   // half matrix smem stride
#define SC 68   // float C smem stride
#define SB2 40  // readout B stride
#define SC2 36  // readout C stride

#define CAP_F 2176   // record-staging capacity in k_fused (aliases Cs: 64*68*4/8)
#define CAP_R 1792   // record-staging capacity in readout (aliases W0H+Cs2)

// -------------------- deg + hist + rank (one packed 64b atomic) --------------------
__global__ void k_deg_hist(const int* __restrict__ dst, const float* __restrict__ w, int E) {
    int e = blockIdx.x * blockDim.x + threadIdx.x;
    if (e < E) {
        int d = dst[e];
        unsigned long long add =
            (1ull << 40) | (unsigned long long)__float2uint_rn(w[e] * Q24);
        unsigned long long old = atomicAdd(&g_packed[d], add);
        g_rank[e] = (int)(old >> 40);
    }
}

// -------------------- single-pass decoupled-lookback scan (over PADDED counts) ------
__global__ __launch_bounds__(1024) void k_scan(int n) {
    __shared__ int ws[32];
    __shared__ int prefix_s;
    int b = blockIdx.x, t = threadIdx.x;
    int i = b * 1024 + t;
    unsigned long long pk = (i < n) ? g_packed[i] : 0ull;
    int c = (int)(pk >> 40);
    int cpad = (c + 3) & ~3;                // pad bucket to multiple of 4 edges
    if (i < n) g_packed[i] = 0ull;          // reset for next launch

    const unsigned full = 0xffffffffu;
    int lane = t & 31, warp = t >> 5;
    int x = cpad;
    #pragma unroll
    for (int off = 1; off < 32; off <<= 1) {
        int y = __shfl_up_sync(full, x, off);
        if (lane >= off) x += y;
    }
    if (lane == 31) ws[warp] = x;
    __syncthreads();
    if (warp == 0) {
        int y = ws[lane];
        #pragma unroll
        for (int off = 1; off < 32; off <<= 1) {
            int z = __shfl_up_sync(full, y, off);
            if (lane >= off) y += z;
        }
        ws[lane] = y;
    }
    __syncthreads();
    int blockpref = (warp > 0) ? ws[warp - 1] : 0;
    int incl = x + blockpref;

    if (t == 1023) {
        unsigned long long p = (1ull << 32) | (unsigned)incl;
        *((volatile unsigned long long*)&g_lbpack[b]) = p;
    }
    if (t == 0) prefix_s = 0;
    __syncthreads();
    if (t < b) {
        unsigned long long p;
        do { p = *((volatile unsigned long long*)&g_lbpack[t]); } while (!(p >> 32));
        atomicAdd(&prefix_s, (int)(unsigned)p);
    }
    __syncthreads();

    int excl = incl - cpad + prefix_s;
    if (i < n) {
        g_row[i] = excl;
        float deg = 1.0f + (float)(pk & 0xFFFFFFFFFFull) * (1.0f / Q24);
        float dinv = rsqrtf(deg);
        g_deg[i] = dinv;
        int2 ni; ni.x = excl; ni.y = __float_as_int(dinv);
        g_nodeinfo[i] = ni;
        int2 z; z.x = 0; z.y = 0;          // half2(0,0) pad: contributes exactly 0
        for (int k = c; k < cpad; k++) g_edge[excl + k] = z;
    }
    if (i == n) g_row[n] = excl;
}

// -------------------- merged: CSR fill + layer-0 GEMM (wmma) --------------------
__global__ __launch_bounds__(256) void k_fill_gemm0(
    const int* __restrict__ src, const int* __restrict__ dst,
    const float* __restrict__ w, int E,
    const float* __restrict__ X, const float* __restrict__ W, int n,
    int gemm_blocks)
{
    __shared__ __half WsH[64 * SA];
    __shared__ __half XsH[64 * SA];
    __shared__ float Cs[64 * SC];

    int tid = threadIdx.x;

    if (blockIdx.x >= gemm_blocks) {
        // ---- fill part (norm stored as duplicated half2) ----
        int e = (blockIdx.x - gemm_blocks) * 256 + tid;
        if (e < E) {
            int s = src[e], d = dst[e];
            int2 di = __ldg(g_nodeinfo + d);
            float nv = __ldg(g_deg + s) * w[e] * __int_as_float(di.y);
            int pos = di.x + g_rank[e];
            __half2 nh2 = __half2half2(__float2half_rn(nv));
            int2 rec; rec.x = s << 7; rec.y = *(int*)&nh2;
            g_edge[pos] = rec;
        }
        return;
    }

    // ---- gemm0: xwA = X @ W0 via wmma ----
    int row0 = blockIdx.x * 64;

    const float4* W4 = (const float4*)W;
    #pragma unroll
    for (int i = 0; i < 4; i++) {
        int idx = tid + 256 * i;
        float4 f = W4[idx];
        int k = idx >> 4, c4 = idx & 15;
        __half2 h0 = __floats2half2_rn(f.x, f.y);
        __half2 h1 = __floats2half2_rn(f.z, f.w);
        uint2 u; u.x = *(unsigned*)&h0; u.y = *(unsigned*)&h1;
        *(uint2*)&WsH[k * SA + c4 * 4] = u;
    }
    const float4* X4 = (const float4*)(X + (size_t)row0 * 64);
    #pragma unroll
    for (int i = 0; i < 4; i++) {
        int idx = tid + 256 * i;
        int r = idx >> 4, c4 = idx & 15;
        if (row0 + r < n) {
            float4 f = X4[idx];
            __half2 h0 = __floats2half2_rn(f.x, f.y);
            __half2 h1 = __floats2half2_rn(f.z, f.w);
            uint2 u; u.x = *(unsigned*)&h0; u.y = *(unsigned*)&h1;
            *(uint2*)&XsH[r * SA + c4 * 4] = u;
        }
    }
    __syncthreads();

    int wp = tid >> 5;
    int tile_r = wp & 3;
    #pragma unroll
    for (int t2 = 0; t2 < 2; t2++) {
        int tile_c = (wp >> 2) * 2 + t2;
        wmma::fragment<wmma::accumulator, 16, 16, 16, float> cf;
        wmma::fill_fragment(cf, 0.f);
        #pragma unroll
        for (int kk = 0; kk < 4; kk++) {
            wmma::fragment<wmma::matrix_a, 16, 16, 16, __half, wmma::row_major> af;
            wmma::fragment<wmma::matrix_b, 16, 16, 16, __half, wmma::row_major> bf;
            wmma::load_matrix_sync(af, XsH + tile_r * 16 * SA + kk * 16, SA);
            wmma::load_matrix_sync(bf, WsH + kk * 16 * SA + tile_c * 16, SA);
            wmma::mma_sync(cf, af, bf, cf);
        }
        wmma::store_matrix_sync(Cs + tile_r * 16 * SC + tile_c * 16, cf, SC, wmma::mem_row_major);
    }
    __syncthreads();

    int r = tid >> 2, c0 = (tid & 3) * 16;
    int row = row0 + r;
    if (row >= n) return;
    const float* crow = &Cs[r * SC + c0];
    __half2 hh[8];
    #pragma unroll
    for (int i = 0; i < 8; i++) hh[i] = __floats2half2_rn(crow[2 * i], crow[2 * i + 1]);
    uint4* dstp = (uint4*)(g_xwA + (size_t)row * 64 + c0);
    dstp[0] = ((uint4*)hh)[0];
    dstp[1] = ((uint4*)hh)[1];
}

// ---- fp16 group accumulate (4 edges) + fp32 flush ----
#define GROUP_ACC() do { \
    const __half2* h0 = (const __half2*)&u0; \
    const __half2* h1 = (const __half2*)&u1; \
    const __half2* h2 = (const __half2*)&u2; \
    const __half2* h3 = (const __half2*)&u3; \
    __half2 s0 = __hmul2(h0[0], n0), s1 = __hmul2(h0[1], n0); \
    __half2 s2 = __hmul2(h0[2], n0), s3 = __hmul2(h0[3], n0); \
    s0 = __hfma2(h1[0], n1, s0); s1 = __hfma2(h1[1], n1, s1); \
    s2 = __hfma2(h1[2], n1, s2); s3 = __hfma2(h1[3], n1, s3); \
    s0 = __hfma2(h2[0], n2, s0); s1 = __hfma2(h2[1], n2, s1); \
    s2 = __hfma2(h2[2], n2, s2); s3 = __hfma2(h2[3], n2, s3); \
    s0 = __hfma2(h3[0], n3, s0); s1 = __hfma2(h3[1], n3, s1); \
    s2 = __hfma2(h3[2], n3, s2); s3 = __hfma2(h3[3], n3, s3); \
    float2 f; \
    f = __half22float2(s0); a[0] += f.x; a[1] += f.y; \
    f = __half22float2(s1); a[2] += f.x; a[3] += f.y; \
    f = __half22float2(s2); a[4] += f.x; a[5] += f.y; \
    f = __half22float2(s3); a[6] += f.x; a[7] += f.y; \
} while (0)

// ---- gather core: 8 threads/node; records from SMEM staging (global fallback) ----
__device__ __forceinline__ void gather_core8(const __half* __restrict__ xwh,
                                             int node, int j,
                                             const float* __restrict__ bias,
                                             float* a /*[8]*/,
                                             const int2* __restrict__ recS,
                                             int s0, int stage)
{
    int2 ni = __ldg(g_nodeinfo + node);      // (padded start, dinv)
    int start = ni.x;
    int end   = __ldg(g_row + node + 1);
    float dv = __int_as_float(ni.y);
    float inv = dv * dv;

    const char* base = (const char*)xwh + (j << 4);

    // bias + self-loop in fp32 (exact path)
    {
        uint4 v = __ldg((const uint4*)(base + ((unsigned)node << 7)));
        const __half2* h = (const __half2*)&v;
        const float4* b4 = (const float4*)(bias + j * 8);
        float4 b0 = __ldg(b4), b1 = __ldg(b4 + 1);
        float2 f0 = __half22float2(h[0]), f1 = __half22float2(h[1]);
        float2 f2 = __half22float2(h[2]), f3 = __half22float2(h[3]);
        a[0] = f0.x * inv + b0.x; a[1] = f0.y * inv + b0.y;
        a[2] = f1.x * inv + b0.z; a[3] = f1.y * inv + b0.w;
        a[4] = f2.x * inv + b1.x; a[5] = f2.y * inv + b1.y;
        a[6] = f3.x * inv + b1.z; a[7] = f3.y * inv + b1.w;
    }

    int cnt = end - start;                    // multiple of 4
    int groups = cnt >> 2;
    int rel = start - s0;

    if (rel + cnt <= stage) {
        // fast path: records from shared memory (LDS latency ~29cyc)
        const int4* rp = (const int4*)(recS + rel);   // 16B-aligned (rel mult of 4)
        for (int gq = 0; gq < groups; gq++) {
            int4 r01 = rp[0];
            int4 r23 = rp[1];
            rp += 2;
            uint4 u0 = __ldg((const uint4*)(base + (unsigned)r01.x));
            uint4 u1 = __ldg((const uint4*)(base + (unsigned)r01.z));
            uint4 u2 = __ldg((const uint4*)(base + (unsigned)r23.x));
            uint4 u3 = __ldg((const uint4*)(base + (unsigned)r23.z));
            __half2 n0 = *(__half2*)&r01.y, n1 = *(__half2*)&r01.w;
            __half2 n2 = *(__half2*)&r23.y, n3 = *(__half2*)&r23.w;
            GROUP_ACC();
        }
    } else {
        // rare fallback: records from global
        const int4* ep = (const int4*)(g_edge + start);
        for (int gq = 0; gq < groups; gq++) {
            int4 r01 = __ldg(ep);
            int4 r23 = __ldg(ep + 1);
            ep += 2;
            uint4 u0 = __ldg((const uint4*)(base + (unsigned)r01.x));
            uint4 u1 = __ldg((const uint4*)(base + (unsigned)r01.z));
            uint4 u2 = __ldg((const uint4*)(base + (unsigned)r23.x));
            uint4 u3 = __ldg((const uint4*)(base + (unsigned)r23.z));
            __half2 n0 = *(__half2*)&r01.y, n1 = *(__half2*)&r01.w;
            __half2 n2 = *(__half2*)&r23.y, n3 = *(__half2*)&r23.w;
            GROUP_ACC();
        }
    }
}

// -------------------- fused: stage records -> gather -> wmma @W -> xw out ----------
__global__ __launch_bounds__(512, 3) void k_fused(
    const float* __restrict__ bias, const float* __restrict__ W,
    int in_is_A, int n)
{
    __shared__ __half WsH[64 * SA];
    __shared__ __half XsH[64 * SA];
    __shared__ union { float Cs[64 * SC]; int2 rec[CAP_F]; } U;   // rec dead before Cs lives

    const __half* xin = in_is_A ? g_xwA : g_xwB;
    __half* xout      = in_is_A ? g_xwB : g_xwA;

    int tid = threadIdx.x;
    int row0 = blockIdx.x * 64;

    const float4* W4 = (const float4*)W;
    #pragma unroll
    for (int i = 0; i < 2; i++) {
        int idx = tid + 512 * i;
        float4 f = W4[idx];
        int k = idx >> 4, c4 = idx & 15;
        __half2 h0 = __floats2half2_rn(f.x, f.y);
        __half2 h1 = __floats2half2_rn(f.z, f.w);
        uint2 u; u.x = *(unsigned*)&h0; u.y = *(unsigned*)&h1;
        *(uint2*)&WsH[k * SA + c4 * 4] = u;
    }

    // stage this block's record range into smem (coalesced bulk copy)
    int hi = row0 + 64; if (hi > n) hi = n;
    int s0 = __ldg(g_row + row0);
    int s1 = __ldg(g_row + hi);
    int total = s1 - s0;                       // multiple of 4
    int stage = total < CAP_F ? total : CAP_F;
    const int4* gsrc = (const int4*)(g_edge + s0);
    for (int i = tid; i < (stage >> 1); i += 512)
        ((int4*)U.rec)[i] = __ldg(gsrc + i);
    __syncthreads();

    int node_l = tid >> 3;
    int j = tid & 7;
    int node = row0 + node_l;

    if (node < n) {
        float a[8];
        gather_core8(xin, node, j, bias, a, U.rec, s0, stage);
        __half2 hh[4];
        #pragma unroll
        for (int q = 0; q < 4; q++)
            hh[q] = __floats2half2_rn(fmaxf(a[2 * q], 0.f), fmaxf(a[2 * q + 1], 0.f));
        *(uint4*)&XsH[node_l * SA + j * 8] = *(uint4*)hh;
    } else {
        uint4 z = {0, 0, 0, 0};
        *(uint4*)&XsH[node_l * SA + j * 8] = z;
    }
    __syncthreads();   // gather (rec reads) done before Cs (alias) is written

    {
        int wp = tid >> 5;
        int tile_r = wp & 3, tile_c = wp >> 2;
        wmma::fragment<wmma::accumulator, 16, 16, 16, float> cf;
        wmma::fill_fragment(cf, 0.f);
        #pragma unroll
        for (int kk = 0; kk < 4; kk++) {
            wmma::fragment<wmma::matrix_a, 16, 16, 16, __half, wmma::row_major> af;
            wmma::fragment<wmma::matrix_b, 16, 16, 16, __half, wmma::row_major> bf;
            wmma::load_matrix_sync(af, XsH + tile_r * 16 * SA + kk * 16, SA);
            wmma::load_matrix_sync(bf, WsH + kk * 16 * SA + tile_c * 16, SA);
            wmma::mma_sync(cf, af, bf, cf);
        }
        wmma::store_matrix_sync(U.Cs + tile_r * 16 * SC + tile_c * 16, cf, SC, wmma::mem_row_major);
    }
    __syncthreads();

    if (node >= n) return;
    const float* crow = &U.Cs[node_l * SC + j * 8];
    __half2 hh[4];
    #pragma unroll
    for (int q = 0; q < 4; q++) hh[q] = __floats2half2_rn(crow[2 * q], crow[2 * q + 1]);
    *(uint4*)(xout + (size_t)node * 64 + j * 8) = *(uint4*)hh;
}

// -------------------- final: stage -> gather -> wmma MLP readout -> pooled mean -----
__global__ __launch_bounds__(512, 3) void k_gather_readout(
    const float* __restrict__ bias,
    const float* __restrict__ Wr0, const float* __restrict__ br0,
    const float* __restrict__ Wr1, const float* __restrict__ br1,
    const int* __restrict__ batch, int n)
{
    __shared__ __half aggH[64 * SA];
    __shared__ union {
        struct { __half W0H[64 * SB2]; float Cs2[64 * SC2]; } p;
        int2 rec[CAP_R];
    } U;                                   // rec dead before W0H/Cs2 live
    __shared__ float W1s[32];
    __shared__ float b0s[32];

    int tid = threadIdx.x;
    if (tid < 32) { W1s[tid] = Wr1[tid]; b0s[tid] = br0[tid]; }

    int row0 = blockIdx.x * 64;
    int hi = row0 + 64; if (hi > n) hi = n;
    int s0 = __ldg(g_row + row0);
    int s1 = __ldg(g_row + hi);
    int total = s1 - s0;
    int stage = total < CAP_R ? total : CAP_R;
    const int4* gsrc = (const int4*)(g_edge + s0);
    for (int i = tid; i < (stage >> 1); i += 512)
        ((int4*)U.rec)[i] = __ldg(gsrc + i);
    __syncthreads();

    int node_l = tid >> 3;
    int j = tid & 7;
    int node = row0 + node_l;
    bool valid = (node < n);

    if (valid) {
        float a[8];
        gather_core8(g_xwA, node, j, bias, a, U.rec, s0, stage);   // no relu (last layer)
        __half2 hh[4];
        #pragma unroll
        for (int q = 0; q < 4; q++) hh[q] = __floats2half2_rn(a[2 * q], a[2 * q + 1]);
        *(uint4*)&aggH[node_l * SA + j * 8] = *(uint4*)hh;
    } else {
        uint4 z = {0, 0, 0, 0};
        *(uint4*)&aggH[node_l * SA + j * 8] = z;
    }
    __syncthreads();   // rec reads done; W0H (alias) may now be written

    // load Wr0 into smem (after gather: aliases the record buffer)
    {
        const float4* W4 = (const float4*)Wr0;
        float4 f = W4[tid];
        int k = tid >> 3, c4 = tid & 7;
        __half2 h0 = __floats2half2_rn(f.x, f.y);
        __half2 h1 = __floats2half2_rn(f.z, f.w);
        uint2 u; u.x = *(unsigned*)&h0; u.y = *(unsigned*)&h1;
        *(uint2*)&U.p.W0H[k * SB2 + c4 * 4] = u;
    }
    __syncthreads();

    {
        int wp = tid >> 5;
        if (wp < 8) {
            int tile_r = wp & 3, tile_c = wp >> 2;
            wmma::fragment<wmma::accumulator, 16, 16, 16, float> cf;
            wmma::fill_fragment(cf, 0.f);
            #pragma unroll
            for (int kk = 0; kk < 4; kk++) {
                wmma::fragment<wmma::matrix_a, 16, 16, 16, __half, wmma::row_major> af;
                wmma::fragment<wmma::matrix_b, 16, 16, 16, __half, wmma::row_major> bf;
                wmma::load_matrix_sync(af, aggH + tile_r * 16 * SA + kk * 16, SA);
                wmma::load_matrix_sync(bf, U.p.W0H + kk * 16 * SB2 + tile_c * 16, SB2);
                wmma::mma_sync(cf, af, bf, cf);
            }
            wmma::store_matrix_sync(U.p.Cs2 + tile_r * 16 * SC2 + tile_c * 16, cf, SC2,
                                    wmma::mem_row_major);
        }
    }
    __syncthreads();

    float s = 0.f, cv = 0.f;
    int g = -1;
    if (valid) {
        int c0 = j * 4;
        const float* crow = &U.p.Cs2[node_l * SC2 + c0];
        const float4 w1 = *(const float4*)&W1s[c0];
        float a0 = crow[0] + b0s[c0 + 0];
        float a1 = crow[1] + b0s[c0 + 1];
        float a2 = crow[2] + b0s[c0 + 2];
        float a3 = crow[3] + b0s[c0 + 3];
        s = fmaxf(a0, 0.f) * w1.x + fmaxf(a1, 0.f) * w1.y
          + fmaxf(a2, 0.f) * w1.z + fmaxf(a3, 0.f) * w1.w;
        g = __ldg(batch + node);   // all 8 lanes keep g (segment contiguity)
    }

    const unsigned full = 0xffffffffu;
    s += __shfl_xor_sync(full, s, 4);
    s += __shfl_xor_sync(full, s, 2);
    s += __shfl_xor_sync(full, s, 1);

    if (valid && j == 0) { s += __ldg(br1); cv = 1.f; }
    else { s = 0.f; cv = 0.f; }

    int lane = tid & 31;
    #pragma unroll
    for (int off = 1; off < 32; off <<= 1) {
        float so = __shfl_up_sync(full, s, off);
        float co = __shfl_up_sync(full, cv, off);
        int go = __shfl_up_sync(full, g, off);
        if (lane >= off && go == g) { s += so; cv += co; }
    }
    int gn = __shfl_down_sync(full, g, 1);
    if ((lane == 31 || gn != g) && g >= 0) {
        atomicAdd(&g_sums[g], s);
        atomicAdd(&g_cnt[g], cv);
    }
}

// finalize output + reset accumulators/lookback for next launch
__global__ void k_finalize(float* __restrict__ out) {
    int g = threadIdx.x;
    out[g] = g_sums[g] / fmaxf(g_cnt[g], 1.0f);
    g_sums[g] = 0.f;
    g_cnt[g] = 0.f;
    if (g < 128) g_lbpack[g] = 0ull;
}

// -------------------- launch --------------------
extern "C" void kernel_launch(void* const* d_in, const int* in_sizes, int n_in,
                              void* d_out, int out_size)
{
    const float* x   = (const float*)d_in[0];
    const int*   ei  = (const int*)d_in[1];
    const float* ew  = (const float*)d_in[2];
    const int* batch = (const int*)d_in[3];
    const float* W0  = (const float*)d_in[4];
    const float* b0  = (const float*)d_in[5];
    const float* W1  = (const float*)d_in[6];
    const float* b1  = (const float*)d_in[7];
    const float* W2  = (const float*)d_in[8];
    const float* b2  = (const float*)d_in[9];
    const float* Wr0 = (const float*)d_in[10];
    const float* br0 = (const float*)d_in[11];
    const float* Wr1 = (const float*)d_in[12];
    const float* br1 = (const float*)d_in[13];
    float* out = (float*)d_out;

    int n = in_sizes[0] / HID;       // 100000
    int E = in_sizes[2];             // 1600000
    const int* src = ei;
    const int* dst = ei + E;

    int nb = (n + 1023) / 1024;      // 98 blocks: all resident -> lookback safe
    int gb = (n + 63) / 64;          // 1563 gemm/gather blocks
    int fb = (E + 255) / 256;        // 6250 fill blocks

    // launch #3 (0-indexed) is k_fused -> that's what ncu captures
    k_deg_hist<<<fb, 256>>>(dst, ew, E);                                // 0
    k_scan<<<nb, 1024>>>(n);                                            // 1
    k_fill_gemm0<<<gb + fb, 256>>>(src, dst, ew, E, x, W0, n, gb);      // 2
    k_fused<<<gb, 512>>>(b0, W1, 1, n);                                 // 3  <- profiled
    k_fused<<<gb, 512>>>(b1, W2, 0, n);                                 // 4
    k_gather_readout<<<gb, 512>>>(b2, Wr0, br0, Wr1, br1, batch, n);    // 5
    k_finalize<<<1, 256>>>(out);                                        // 6
}